// round 14
// baseline (speedup 1.0000x reference)
#include <cuda_runtime.h>
#include <cstdint>

// CrossMerge3D: out[b,c,i,j,k] = ( sum of 12 scans in 3 orientations ) / 12
//   family i (s=0..3):  n = i*1024 + j*32 + k   (fwd s0,s1; flipped s2,s3)
//   family j (s=4..7):  n = j*1024 + k*32 + i
//   family k (s=8..11): n = k*1024 + i*32 + j
//
// Block = (b, c, j-half, i-quarter): 8i x 16j x 32k = 4096 cells, grid 1536.
// Same wavefront-optimal shape + swizzle as the 55.8us kernel. Changes:
//   - #pragma unroll 2 on all phase loops: 8-load/thread in-flight window
//     (proven sufficient by the ITERS=2 variant) -> natural regs ~34-36
//   - __launch_bounds__(256, 7): 7 blocks/SM = 56 warps (87.5% theoretical)
// smem: f(row,k) = row*36 + (k ^ s(row)), row = ii*16+jl,
//       s = (8*((row>>2)&3)) ^ (16*(row>>6))

#define DD      32
#define NVOL    32768            // 32^3
#define CCH     96
#define CN      (CCH * NVOL)     // 3145728
#define THREADS 256
#define ITERS   4                // 1024 float4-chunks per family / 256 threads

__global__ __launch_bounds__(THREADS, 7)
void cross_merge3d_kernel(const float* __restrict__ ys, float* __restrict__ out) {
    __shared__ __align__(16) float acc[128 * 36];   // 4608 floats (18.4KB)

    const int bid = blockIdx.x;
    const int ia  = bid & 3;                  // i-quarter (i = 8*ia + ii)
    const int jh  = (bid >> 2) & 1;           // j-half
    const int c   = (bid >> 3) % CCH;
    const int b   = bid / (8 * CCH);
    const int tid = threadIdx.x;
    const int job = jh * 16;                  // j offset

    const float* base = ys + (size_t)b * (12 * (size_t)CN) + (size_t)c * NVOL;

    // ---------------- Phase 1: family j (s = 4..7), init accumulator ----------------
    // n = j*1024 + k*32 + i; float4 covers i = 8*ia + 4*ih4 .. +3
    {
        const float* q4 = base + 4 * (size_t)CN;
        const float* q5 = base + 5 * (size_t)CN;
        const float* q6 = base + 6 * (size_t)CN;
        const float* q7 = base + 7 * (size_t)CN;
        #pragma unroll 2
        for (int it = 0; it < ITERS; it++) {
            int chunk = it * THREADS + tid;
            int ih4 = chunk & 1;
            int kj  = (chunk >> 1) & 31;
            int jl  = chunk >> 6;             // 0..15
            int m   = (job + jl) * 1024 + kj * 32 + ia * 8 + 4 * ih4;
            float4 f4 = *(const float4*)(q4 + m);
            float4 f5 = *(const float4*)(q5 + m);
            int r_m = NVOL - 4 - m;
            float4 r6 = *(const float4*)(q6 + r_m);
            float4 r7 = *(const float4*)(q7 + r_m);
            int sw = (8 * ((jl >> 2) & 3)) ^ (16 * ih4);
            int f0 = (ih4 * 64 + jl) * 36 + (kj ^ sw);   // row(e) = 64*ih4+16*e+jl
            acc[f0 +    0] = f4.x + f5.x + r6.w + r7.w;
            acc[f0 +  576] = f4.y + f5.y + r6.z + r7.z;
            acc[f0 + 1152] = f4.z + f5.z + r6.y + r7.y;
            acc[f0 + 1728] = f4.w + f5.w + r6.x + r7.x;
        }
    }
    __syncthreads();

    // ---------------- Phase 2: family k (s = 8..11), acc += ----------------
    // n = k*1024 + i*32 + j; float4 covers j = job + 4*j4 .. +3
    {
        const float* q8  = base + 8  * (size_t)CN;
        const float* q9  = base + 9  * (size_t)CN;
        const float* q10 = base + 10 * (size_t)CN;
        const float* q11 = base + 11 * (size_t)CN;
        #pragma unroll 2
        for (int it = 0; it < ITERS; it++) {
            int chunk = it * THREADS + tid;
            int j4 = chunk & 3;
            int kk = (chunk >> 2) & 31;
            int ii = chunk >> 7;              // 0..7
            int m  = kk * 1024 + (ia * 8 + ii) * 32 + job + 4 * j4;
            float4 f8 = *(const float4*)(q8  + m);
            float4 f9 = *(const float4*)(q9  + m);
            int r_m = NVOL - 4 - m;
            float4 rA = *(const float4*)(q10 + r_m);
            float4 rB = *(const float4*)(q11 + r_m);
            int sw = (8 * j4) ^ (16 * (ii >> 2));
            int f0 = (ii * 16 + 4 * j4) * 36 + (kk ^ sw);   // row(e) = ii*16+4*j4+e
            acc[f0 +   0] += f8.x + f9.x + rA.w + rB.w;
            acc[f0 +  36] += f8.y + f9.y + rA.z + rB.z;
            acc[f0 +  72] += f8.z + f9.z + rA.y + rB.y;
            acc[f0 + 108] += f8.w + f9.w + rA.x + rB.x;
        }
    }
    __syncthreads();

    // ---------------- Phase 3: family i (s = 0..3) + fused epilogue ----------------
    // n = i*1024 + j*32 + k; threads own contiguous k -> LDS.128 + STG.128
    {
        const float* q0 = base + 0 * (size_t)CN;
        const float* q1 = base + 1 * (size_t)CN;
        const float* q2 = base + 2 * (size_t)CN;
        const float* q3 = base + 3 * (size_t)CN;
        float* obc = out + ((size_t)b * CCH + c) * NVOL;
        const float s12 = 1.0f / 12.0f;
        #pragma unroll 2
        for (int it = 0; it < ITERS; it++) {
            int chunk = it * THREADS + tid;
            int k4 = chunk & 7;
            int jl = (chunk >> 3) & 15;
            int ii = chunk >> 7;              // 0..7
            int n_g = (ia * 8 + ii) * 1024 + (job + jl) * 32 + 4 * k4;
            float4 f0 = *(const float4*)(q0 + n_g);
            float4 f1 = *(const float4*)(q1 + n_g);
            int r_g = NVOL - 4 - n_g;
            float4 r2 = *(const float4*)(q2 + r_g);
            float4 r3 = *(const float4*)(q3 + r_g);
            int sw = (8 * ((jl >> 2) & 3)) ^ (16 * (ii >> 2));
            int f  = (ii * 16 + jl) * 36 + ((4 * k4) ^ sw);  // 16B-aligned
            float4 av = *(const float4*)(acc + f);
            float4 o;
            o.x = (av.x + f0.x + f1.x + r2.w + r3.w) * s12;
            o.y = (av.y + f0.y + f1.y + r2.z + r3.z) * s12;
            o.z = (av.z + f0.z + f1.z + r2.y + r3.y) * s12;
            o.w = (av.w + f0.w + f1.w + r2.x + r3.x) * s12;
            __stcs((float4*)(obc + n_g), o);
        }
    }
}

extern "C" void kernel_launch(void* const* d_in, const int* in_sizes, int n_in,
                              void* d_out, int out_size) {
    const float* ys = (const float*)d_in[0];
    float* out = (float*)d_out;
    // grid = B * C * j-halves * i-quarters = 2 * 96 * 2 * 4 = 1536
    cross_merge3d_kernel<<<1536, THREADS>>>(ys, out);
}

// round 15
// speedup vs baseline: 1.0764x; 1.0764x over previous
#include <cuda_runtime.h>
#include <cstdint>

// CrossMerge3D: out[b,c,i,j,k] = ( sum of 12 scans in 3 orientations ) / 12
//   family i (s=0..3):  n = i*1024 + j*32 + k   (fwd s0,s1; flipped s2,s3)
//   family j (s=4..7):  n = j*1024 + k*32 + i
//   family k (s=8..11): n = k*1024 + i*32 + j
//
// Block = (b, c, j-half, i-quarter): 8i x 16j x 32k = 4096 cells, grid 1536.
// Identical to the 55.8us kernel (wavefront-optimal split, XOR-swizzled smem,
// fused float4 __stcs epilogue, natural 40 regs / 6 blocks/SM), plus
// prefetch.global.L2 of the NEXT phase's first two iterations issued before
// each __syncthreads(): the post-barrier cold restart hits L2 (~250cy)
// instead of DRAM (~600cy), and the prefetches keep DRAM demand continuous
// across the phase boundary. No registers held across barriers.

#define DD      32
#define NVOL    32768            // 32^3
#define CCH     96
#define CN      (CCH * NVOL)     // 3145728
#define THREADS 256
#define ITERS   4                // 1024 float4-chunks per family / 256 threads

__device__ __forceinline__ void pf_l2(const float* p) {
    asm volatile("prefetch.global.L2 [%0];" :: "l"(p));
}

__global__ __launch_bounds__(THREADS)
void cross_merge3d_kernel(const float* __restrict__ ys, float* __restrict__ out) {
    __shared__ __align__(16) float acc[128 * 36];   // 4608 floats (18.4KB)

    const int bid = blockIdx.x;
    const int ia  = bid & 3;                  // i-quarter (i = 8*ia + ii)
    const int jh  = (bid >> 2) & 1;           // j-half
    const int c   = (bid >> 3) % CCH;
    const int b   = bid / (8 * CCH);
    const int tid = threadIdx.x;
    const int job = jh * 16;                  // j offset

    const float* base = ys + (size_t)b * (12 * (size_t)CN) + (size_t)c * NVOL;

    const float* q8  = base + 8  * (size_t)CN;
    const float* q9  = base + 9  * (size_t)CN;
    const float* q10 = base + 10 * (size_t)CN;
    const float* q11 = base + 11 * (size_t)CN;

    // ---------------- Phase 1: family j (s = 4..7), init accumulator ----------------
    // n = j*1024 + k*32 + i; float4 covers i = 8*ia + 4*ih4 .. +3
    {
        const float* q4 = base + 4 * (size_t)CN;
        const float* q5 = base + 5 * (size_t)CN;
        const float* q6 = base + 6 * (size_t)CN;
        const float* q7 = base + 7 * (size_t)CN;
        #pragma unroll
        for (int it = 0; it < ITERS; it++) {
            int chunk = it * THREADS + tid;
            int ih4 = chunk & 1;
            int kj  = (chunk >> 1) & 31;
            int jl  = chunk >> 6;             // 0..15
            int m   = (job + jl) * 1024 + kj * 32 + ia * 8 + 4 * ih4;
            float4 f4 = *(const float4*)(q4 + m);
            float4 f5 = *(const float4*)(q5 + m);
            int r_m = NVOL - 4 - m;
            float4 r6 = *(const float4*)(q6 + r_m);
            float4 r7 = *(const float4*)(q7 + r_m);
            int sw = (8 * ((jl >> 2) & 3)) ^ (16 * ih4);
            int f0 = (ih4 * 64 + jl) * 36 + (kj ^ sw);   // row(e) = 64*ih4+16*e+jl
            acc[f0 +    0] = f4.x + f5.x + r6.w + r7.w;
            acc[f0 +  576] = f4.y + f5.y + r6.z + r7.z;
            acc[f0 + 1152] = f4.z + f5.z + r6.y + r7.y;
            acc[f0 + 1728] = f4.w + f5.w + r6.x + r7.x;
        }
    }
    // Prefetch phase-2 iterations 0..1 into L2 before the barrier.
    #pragma unroll
    for (int it = 0; it < 2; it++) {
        int chunk = it * THREADS + tid;
        int j4 = chunk & 3;
        int kk = (chunk >> 2) & 31;
        int ii = chunk >> 7;
        int m  = kk * 1024 + (ia * 8 + ii) * 32 + job + 4 * j4;
        int r_m = NVOL - 4 - m;
        pf_l2(q8 + m);  pf_l2(q9 + m);  pf_l2(q10 + r_m);  pf_l2(q11 + r_m);
    }
    __syncthreads();

    // ---------------- Phase 2: family k (s = 8..11), acc += ----------------
    // n = k*1024 + i*32 + j; float4 covers j = job + 4*j4 .. +3
    {
        #pragma unroll
        for (int it = 0; it < ITERS; it++) {
            int chunk = it * THREADS + tid;
            int j4 = chunk & 3;
            int kk = (chunk >> 2) & 31;
            int ii = chunk >> 7;              // 0..7
            int m  = kk * 1024 + (ia * 8 + ii) * 32 + job + 4 * j4;
            float4 f8 = *(const float4*)(q8  + m);
            float4 f9 = *(const float4*)(q9  + m);
            int r_m = NVOL - 4 - m;
            float4 rA = *(const float4*)(q10 + r_m);
            float4 rB = *(const float4*)(q11 + r_m);
            int sw = (8 * j4) ^ (16 * (ii >> 2));
            int f0 = (ii * 16 + 4 * j4) * 36 + (kk ^ sw);   // row(e) = ii*16+4*j4+e
            acc[f0 +   0] += f8.x + f9.x + rA.w + rB.w;
            acc[f0 +  36] += f8.y + f9.y + rA.z + rB.z;
            acc[f0 +  72] += f8.z + f9.z + rA.y + rB.y;
            acc[f0 + 108] += f8.w + f9.w + rA.x + rB.x;
        }
    }
    // Prefetch phase-3 iterations 0..1 into L2 before the barrier.
    {
        const float* q0 = base + 0 * (size_t)CN;
        const float* q1 = base + 1 * (size_t)CN;
        const float* q2 = base + 2 * (size_t)CN;
        const float* q3 = base + 3 * (size_t)CN;
        #pragma unroll
        for (int it = 0; it < 2; it++) {
            int chunk = it * THREADS + tid;
            int k4 = chunk & 7;
            int jl = (chunk >> 3) & 15;
            int ii = chunk >> 7;
            int n_g = (ia * 8 + ii) * 1024 + (job + jl) * 32 + 4 * k4;
            int r_g = NVOL - 4 - n_g;
            pf_l2(q0 + n_g);  pf_l2(q1 + n_g);  pf_l2(q2 + r_g);  pf_l2(q3 + r_g);
        }
    }
    __syncthreads();

    // ---------------- Phase 3: family i (s = 0..3) + fused epilogue ----------------
    // n = i*1024 + j*32 + k; threads own contiguous k -> LDS.128 + STG.128
    {
        const float* q0 = base + 0 * (size_t)CN;
        const float* q1 = base + 1 * (size_t)CN;
        const float* q2 = base + 2 * (size_t)CN;
        const float* q3 = base + 3 * (size_t)CN;
        float* obc = out + ((size_t)b * CCH + c) * NVOL;
        const float s12 = 1.0f / 12.0f;
        #pragma unroll
        for (int it = 0; it < ITERS; it++) {
            int chunk = it * THREADS + tid;
            int k4 = chunk & 7;
            int jl = (chunk >> 3) & 15;
            int ii = chunk >> 7;              // 0..7
            int n_g = (ia * 8 + ii) * 1024 + (job + jl) * 32 + 4 * k4;
            float4 f0 = *(const float4*)(q0 + n_g);
            float4 f1 = *(const float4*)(q1 + n_g);
            int r_g = NVOL - 4 - n_g;
            float4 r2 = *(const float4*)(q2 + r_g);
            float4 r3 = *(const float4*)(q3 + r_g);
            int sw = (8 * ((jl >> 2) & 3)) ^ (16 * (ii >> 2));
            int f  = (ii * 16 + jl) * 36 + ((4 * k4) ^ sw);  // 16B-aligned
            float4 av = *(const float4*)(acc + f);
            float4 o;
            o.x = (av.x + f0.x + f1.x + r2.w + r3.w) * s12;
            o.y = (av.y + f0.y + f1.y + r2.z + r3.z) * s12;
            o.z = (av.z + f0.z + f1.z + r2.y + r3.y) * s12;
            o.w = (av.w + f0.w + f1.w + r2.x + r3.x) * s12;
            __stcs((float4*)(obc + n_g), o);
        }
    }
}

extern "C" void kernel_launch(void* const* d_in, const int* in_sizes, int n_in,
                              void* d_out, int out_size) {
    const float* ys = (const float*)d_in[0];
    float* out = (float*)d_out;
    // grid = B * C * j-halves * i-quarters = 2 * 96 * 2 * 4 = 1536
    cross_merge3d_kernel<<<1536, THREADS>>>(ys, out);
}